// round 6
// baseline (speedup 1.0000x reference)
#include <cuda_runtime.h>
#include <math.h>
#include <stdint.h>

#define W_ 192
#define H_ 192
#define D_ 160
#define HW_ (H_ * W_)
#define CHUNK 80
#define NPLANES 84
#define NPAIRS  42
#define NBLOCKS (6 * 12 * 4)

#define BAR_FULL0  1
#define BAR_FULL1  2
#define BAR_EMPTY0 3
#define BAR_EMPTY1 4
#define BAR_PROD   5

__device__ double   g_acc;
__device__ unsigned g_cnt;

static __device__ __forceinline__ void bar_sync_n(int id, int cnt) {
    asm volatile("bar.sync %0, %1;" :: "r"(id), "r"(cnt) : "memory");
}
static __device__ __forceinline__ void bar_arrive_n(int id, int cnt) {
    asm volatile("bar.arrive %0, %1;" :: "r"(id), "r"(cnt) : "memory");
}
static __device__ __forceinline__ void cp_async8(uint32_t dst, const float* src,
                                                 unsigned srcsz) {
    asm volatile("cp.async.ca.shared.global [%0], [%1], 8, %2;"
                 :: "r"(dst), "l"(src), "r"(srcsz) : "memory");
}
static __device__ __forceinline__ void cp_commit() {
    asm volatile("cp.async.commit_group;" ::: "memory");
}
static __device__ __forceinline__ void cp_wait2() {
    asm volatile("cp.async.wait_group 2;" ::: "memory");
}

__global__ void __launch_bounds__(512, 1)
lncc_k(const float* __restrict__ src, const float* __restrict__ tgt,
       float* __restrict__ out)
{
    // tile: 3 pair-buffers x 2 planes x [img][haloRow(20)][col(36 pad 40)]
    __shared__ float tile[3][2][2][20][40];
    // rs: 2 buffers x 2 planes x [ch][haloRow(20)][x(32)]
    __shared__ float rs[2][2][5][20][32];
    __shared__ float wsum[16];

    const int tid = threadIdx.x;
    const int x0  = blockIdx.x * 32;
    const int y0  = blockIdx.y * 16;
    const int b   = blockIdx.z >> 1;
    const int z0  = (blockIdx.z & 1) * CHUNK;
    const int zstart = z0 - 2;

    const float* baseS = src + (size_t)b * (D_ * HW_);
    const float* baseT = tgt + (size_t)b * (D_ * HW_);

    float acc = 0.f;

    if (tid < 256) {
        // ============================ PRODUCER ============================
        // Halo plane: 36 cols x 20 rows x 2 imgs = 720 8B pairs (18 pairs/row).
        uint32_t soffb[3];
        const float* gbase[3];
        unsigned vmask = 0;
        const int nslot = (tid < 208) ? 3 : 2;
        #pragma unroll
        for (int sl = 0; sl < 3; sl++) {
            const int i   = tid + 256 * sl;
            const int img = (i >= 360) ? 1 : 0;
            const int j   = i - img * 360;
            const int row = j / 18;
            const int pc  = j - row * 18;
            soffb[sl] = (uint32_t)(img * 800 + row * 40 + pc * 2) * 4u;
            const int gy = y0 + row - 2;
            const int gx = x0 + pc * 2 - 2;   // even; pairs never straddle W
            const bool v = ((unsigned)gy < (unsigned)H_) &&
                           ((unsigned)gx < (unsigned)W_);
            if (v) vmask |= 1u << sl;
            gbase[sl] = (img ? baseT : baseS) + (v ? (gy * W_ + gx) : 0);
        }

        const uint32_t sbase = (uint32_t)__cvta_generic_to_shared(&tile[0][0][0][0][0]);

        auto issue_pair = [&](int m) {        // planes 2m, 2m+1 -> pairbuf m%3
            const uint32_t pb = sbase + (uint32_t)(m % 3) * 12800u;
            #pragma unroll
            for (int pl = 0; pl < 2; pl++) {
                const int zp  = zstart + 2 * m + pl;
                const bool zin = (unsigned)zp < (unsigned)D_;
                const int zoff = zin ? zp * HW_ : 0;
                const uint32_t tb = pb + (uint32_t)pl * 6400u;
                #pragma unroll
                for (int sl = 0; sl < 3; sl++) {
                    if (sl < nslot) {
                        unsigned sz = (zin && (vmask & (1u << sl))) ? 8u : 0u;
                        cp_async8(tb + soffb[sl], gbase[sl] + zoff, sz);
                    }
                }
            }
            cp_commit();
        };

        // x-phase for one plane: tile plane tb -> rs plane rsq
        auto xphase = [&](const float* tb, float* rsq) {
            const int r  = tid >> 3;
            const int x4 = (tid & 7) << 2;
            const float* rowS = tb + r * 40 + x4;
            const float* rowT = rowS + 800;
            float4 a0 = *(const float4*)(rowS);
            float4 a1 = *(const float4*)(rowS + 4);
            float4 b0 = *(const float4*)(rowT);
            float4 b1 = *(const float4*)(rowT + 4);
            float sc[8] = {a0.x,a0.y,a0.z,a0.w,a1.x,a1.y,a1.z,a1.w};
            float tc[8] = {b0.x,b0.y,b0.z,b0.w,b1.x,b1.y,b1.z,b1.w};
            const int ro = r * 32 + x4;
            {
                float S0=0.f, T0=0.f;
                #pragma unroll
                for (int j = 0; j < 5; j++) { S0 += sc[j]; T0 += tc[j]; }
                float Sv[4], Tv[4];
                Sv[0]=S0; Tv[0]=T0;
                #pragma unroll
                for (int w = 1; w < 4; w++) {
                    Sv[w] = Sv[w-1] - sc[w-1] + sc[w+4];
                    Tv[w] = Tv[w-1] - tc[w-1] + tc[w+4];
                }
                *(float4*)(rsq + 0*640 + ro) = make_float4(Sv[0],Sv[1],Sv[2],Sv[3]);
                *(float4*)(rsq + 1*640 + ro) = make_float4(Tv[0],Tv[1],Tv[2],Tv[3]);
            }
            {
                float SS0=0.f, TT0=0.f;
                #pragma unroll
                for (int j = 0; j < 5; j++) {
                    SS0 = fmaf(sc[j], sc[j], SS0);
                    TT0 = fmaf(tc[j], tc[j], TT0);
                }
                float SSv[4], TTv[4];
                SSv[0]=SS0; TTv[0]=TT0;
                #pragma unroll
                for (int w = 1; w < 4; w++) {
                    SSv[w] = SSv[w-1] - sc[w-1]*sc[w-1] + sc[w+4]*sc[w+4];
                    TTv[w] = TTv[w-1] - tc[w-1]*tc[w-1] + tc[w+4]*tc[w+4];
                }
                *(float4*)(rsq + 2*640 + ro) = make_float4(SSv[0],SSv[1],SSv[2],SSv[3]);
                *(float4*)(rsq + 3*640 + ro) = make_float4(TTv[0],TTv[1],TTv[2],TTv[3]);
            }
            {
                float ST0=0.f;
                #pragma unroll
                for (int j = 0; j < 5; j++) ST0 = fmaf(sc[j], tc[j], ST0);
                float STv[4];
                STv[0]=ST0;
                #pragma unroll
                for (int w = 1; w < 4; w++)
                    STv[w] = STv[w-1] - sc[w-1]*tc[w-1] + sc[w+4]*tc[w+4];
                *(float4*)(rsq + 4*640 + ro) = make_float4(STv[0],STv[1],STv[2],STv[3]);
            }
        };

        // prologue: pairs 0,1 (groups G0,G1)
        issue_pair(0);
        issue_pair(1);

        for (int k = 0; k < NPAIRS; k++) {
            const int q = k & 1;
            // consumers done with rs[q] (pair k-2); 512-wide -> also fences all
            // producers past x-phase of pair k-1, making tile[(k+2)%3] reusable.
            bar_sync_n(BAR_EMPTY0 + q, 512);
            issue_pair(k + 2);
            cp_wait2();                         // pair k's group has landed
            bar_sync_n(BAR_PROD, 256);          // cross-thread visibility

            if (tid < 160) {
                const float* pb = &tile[k % 3][0][0][0][0];
                float* rq = &rs[q][0][0][0][0];
                xphase(pb,        rq);          // plane 2k
                xphase(pb + 1600, rq + 3200);   // plane 2k+1
            }
            bar_arrive_n(BAR_FULL0 + q, 512);   // rs[q] published (pair k)
        }
    } else {
        // ============================ CONSUMER ============================
        const int ctid = tid - 256;
        const int ctx  = ctid & 31;
        const int cty  = ctid >> 5;             // 0..7
        const int yb   = 2 * cty;

        float ring[5][2][5];
        float run[2][5];
        #pragma unroll
        for (int s = 0; s < 5; s++)
            #pragma unroll
            for (int pp = 0; pp < 2; pp++)
                #pragma unroll
                for (int c = 0; c < 5; c++) ring[s][pp][c] = 0.f;
        #pragma unroll
        for (int pp = 0; pp < 2; pp++)
            #pragma unroll
            for (int c = 0; c < 5; c++) run[pp][c] = 0.f;

        // prime both empty buffers (2 pairs = 4 planes of decoupling)
        bar_arrive_n(BAR_EMPTY0, 512);
        bar_arrive_n(BAR_EMPTY1, 512);

        // one plane's worth of consumer work; s = ring slot (compile-time)
        auto consume_plane = [&](const float* rp, int s, bool live) {
            float n0[5], n1[5];
            #pragma unroll
            for (int c = 0; c < 5; c++) {
                const float* col = rp + c * 640 + yb * 32 + ctx;
                float v0 = col[0*32];
                float v1 = col[1*32];
                float v2 = col[2*32];
                float v3 = col[3*32];
                float v4 = col[4*32];
                float v5 = col[5*32];
                float sm = ((v0 + v1) + (v2 + v3)) + v4;
                n0[c] = sm;
                n1[c] = sm - v0 + v5;
            }
            #pragma unroll
            for (int c = 0; c < 5; c++) {
                run[0][c]    += n0[c] - ring[s][0][c];
                ring[s][0][c] = n0[c];
                run[1][c]    += n1[c] - ring[s][1][c];
                ring[s][1][c] = n1[c];
            }
            if (live) {
                const float inv = 1.f / 125.f;
                #pragma unroll
                for (int pp = 0; pp < 2; pp++) {
                    float sm = run[pp][0] * inv;
                    float tm = run[pp][1] * inv;
                    float sv = fmaf(-sm, sm, run[pp][2] * inv);
                    float tv = fmaf(-tm, tm, run[pp][3] * inv);
                    float cr = fmaf(-sm, tm, run[pp][4] * inv);
                    float den = fmaf(sv, tv, 1e-5f);
                    acc += __fdividef(cr * cr, den);
                }
            }
        };

        for (int kb = 0; kb < 45; kb += 5) {
            #pragma unroll
            for (int jj = 0; jj < 5; jj++) {     // compile-time slot pattern
                const int k = kb + jj;
                if (k >= NPAIRS) break;          // 42 = 8*5 + 2
                const int q  = k & 1;
                const int s0 = (2 * jj) % 5;
                const int s1 = (2 * jj + 1) % 5;
                bar_sync_n(BAR_FULL0 + q, 512);

                const float* rq = &rs[q][0][0][0][0];
                // plane 2k (live iff 2k >= 4, i.e. k >= 2)
                consume_plane(rq,        s0, k >= 2);
                // plane 2k+1 (live iff 2k+1 >= 4, i.e. k >= 2)
                consume_plane(rq + 3200, s1, k >= 2);

                bar_arrive_n(BAR_EMPTY0 + q, 512);
            }
        }
    }

    // ---- block reduction over all 512 threads (producers contribute 0) ----
    __syncthreads();
    #pragma unroll
    for (int o = 16; o > 0; o >>= 1)
        acc += __shfl_xor_sync(0xffffffffu, acc, o);
    if ((tid & 31) == 0) wsum[tid >> 5] = acc;
    __syncthreads();

    if (tid == 0) {
        float bsum = 0.f;
        #pragma unroll
        for (int i = 0; i < 16; i++) bsum += wsum[i];
        atomicAdd(&g_acc, (double)bsum);
        __threadfence();
        unsigned done = atomicAdd(&g_cnt, 1u);
        if (done == NBLOCKS - 1) {
            double total = atomicAdd(&g_acc, 0.0);  // fenced read
            const double n = 2.0 * 160.0 * 192.0 * 192.0;
            float loss = (float)(1.0 - total / n);
            if (isnan(loss) || isinf(loss)) loss = 1.0f;
            out[0] = loss;
            *((volatile double*)&g_acc)   = 0.0;
            *((volatile unsigned*)&g_cnt) = 0u;
        }
    }
}

extern "C" void kernel_launch(void* const* d_in, const int* in_sizes, int n_in,
                              void* d_out, int out_size)
{
    (void)in_sizes; (void)n_in; (void)out_size;
    const float* src = (const float*)d_in[0];
    const float* tgt = (const float*)d_in[1];

    lncc_k<<<dim3(6, 12, 4), 512>>>(src, tgt, (float*)d_out);
}